// round 16
// baseline (speedup 1.0000x reference)
#include <cuda_runtime.h>
#include <cstdint>

#define FDIM   1024
#define FV     256            // float4 per row
#define DDOM   8
#define MAXN   16384
#define NSEG   296            // 2 full waves on 148 SMs
#define MAXR   64             // max rows per segment (56)
#define DEPTH  10             // stats cp.async depth (rows in flight)
#define RA     8              // rows per apply block
#define EPSV   1e-5f

// ---------------- scratch ----------------
__device__ float g_P[NSEG * DDOM * FDIM];     // partial sum(x)
__device__ float g_Q[NSEG * DDOM * FDIM];     // partial sum(x*x)
__device__ int   g_c[NSEG * DDOM];            // per-seg domain counts
__device__ unsigned char g_ydom[MAXN];        // decoded domain per row
__device__ float g_A[DDOM * FDIM];            // gamma * inv
__device__ float g_B[DDOM * FDIM];            // beta - mean * gamma * inv

// int64-vs-int32 y detection (odd 32-bit words all zero over 32 values)
__device__ __forceinline__ int detect64(const int* __restrict__ y) {
    const int4* p = (const int4*)y;
    int acc = 0;
#pragma unroll
    for (int i = 0; i < 8; i++) { int4 a = p[i]; acc |= a.y | a.w; }
    return acc == 0;
}

#define ACCUM(v)                                        \
    s1.x += v.x; s1.y += v.y; s1.z += v.z; s1.w += v.w; \
    s2.x = fmaf(v.x, v.x, s2.x);                        \
    s2.y = fmaf(v.y, v.y, s2.y);                        \
    s2.z = fmaf(v.z, v.z, s2.z);                        \
    s2.w = fmaf(v.w, v.w, s2.w);

#define FADD4(acc, p) do {                                      \
    acc.x += (p).x; acc.y += (p).y; acc.z += (p).z; acc.w += (p).w; } while (0)

// ---- K1: stats via cp.async pipeline over domain-sorted flat list ----
__global__ __launch_bounds__(256, 2)
void stats_k(const float4* __restrict__ x4, const int* __restrict__ yi,
             int n, int rlo, int rem) {
    __shared__ float4 buf[DEPTH][256];   // 40 KB ring
    __shared__ int flat[MAXR];           // row*FV, domain-sorted
    __shared__ int cnt[DDOM];
    __shared__ int fill[DDOM];

    const int tid  = threadIdx.x;
    const int b    = blockIdx.x;
    const int base = b * rlo + min(b, rem);
    const int nr   = min(rlo + (b < rem ? 1 : 0), n - base);

    if (tid < DDOM) cnt[tid] = 0;
    __syncthreads();

    if (tid < 32) {   // warp 0: deterministic 2-tile counting sort -> flat[]
        const int is64 = detect64(yi);
        const int r0 = base + tid;
        const int r1 = base + 32 + tid;
        const int da = (tid < nr)      ? (is64 ? yi[2 * r0] : yi[r0]) : -1;
        const int db = (32 + tid < nr) ? (is64 ? yi[2 * r1] : yi[r1]) : -1;
        const unsigned ma = __match_any_sync(0xffffffffu, da);
        if (da >= 0) {
            g_ydom[r0] = (unsigned char)da;
            if ((int)(__ffs(ma) - 1) == tid) cnt[da] = __popc(ma);
        }
        __syncwarp();
        const unsigned mb = __match_any_sync(0xffffffffu, db);
        if (db >= 0) {
            g_ydom[r1] = (unsigned char)db;
            if ((int)(__ffs(mb) - 1) == tid) cnt[db] += __popc(mb);
        }
        __syncwarp();
        if (tid == 0) {
            int run = 0;
#pragma unroll
            for (int d = 0; d < DDOM; d++) { fill[d] = run; run += cnt[d]; }
        }
        __syncwarp();
        const int ra = __popc(ma & ((1u << tid) - 1u));
        if (da >= 0) flat[fill[da] + ra] = r0 * FV;
        __syncwarp();
        if (da >= 0 && (int)(__ffs(ma) - 1) == tid) fill[da] += __popc(ma);
        __syncwarp();
        const int rb = __popc(mb & ((1u << tid) - 1u));
        if (db >= 0) flat[fill[db] + rb] = r1 * FV;
    }
    __syncthreads();

    // PDL: let finalize's grid launch now; it parks at its grid-dep sync
    // until this grid's memory ops complete.
    cudaTriggerProgrammaticLaunchCompletion();

    uint32_t sbuf;
    asm("{ .reg .u64 t; cvta.to.shared.u64 t, %1; cvt.u32.u64 %0, t; }"
        : "=r"(sbuf) : "l"(buf));
    const char* xb = (const char*)x4;
    const uint32_t myoff = tid * 16;

#define ISSUE(k) do {                                                        \
        uint32_t _da = sbuf + ((k) % DEPTH) * 4096 + myoff;                  \
        const void* _g = xb + ((size_t)(flat[(k)] + tid) << 4);              \
        asm volatile("cp.async.cg.shared.global [%0], [%1], 16;"             \
                     :: "r"(_da), "l"(_g) : "memory");                       \
        asm volatile("cp.async.commit_group;" ::: "memory");                 \
    } while (0)

    const int np = min(DEPTH, nr);
    for (int k = 0; k < np; k++) ISSUE(k);
    int issued = np;
    int i = 0;

#pragma unroll
    for (int d = 0; d < DDOM; d++) {
        const int nd = cnt[d];
        float4 s1 = make_float4(0.f, 0.f, 0.f, 0.f);
        float4 s2 = make_float4(0.f, 0.f, 0.f, 0.f);
        for (int k = 0; k < nd; k++, i++) {
            if (issued < nr) {
                asm volatile("cp.async.wait_group %0;" :: "n"(DEPTH - 1) : "memory");
            } else {
                asm volatile("cp.async.wait_group 0;" ::: "memory");
            }
            float4 v = buf[i % DEPTH][tid];
            if (issued < nr) { ISSUE(issued); issued++; }
            ACCUM(v);
        }
        const size_t o = ((size_t)b * DDOM + d) * FV + tid;
        ((float4*)g_P)[o] = s1;
        ((float4*)g_Q)[o] = s2;
    }
    if (tid < DDOM) g_c[b * DDOM + tid] = cnt[tid];
#undef ISSUE
}

// ---- K2: fold segments -> A/B (PDL secondary; triggers apply early) ----
__global__ __launch_bounds__(256)
void finalize_k(const float* __restrict__ gamma, const float* __restrict__ beta,
                int nseg) {
    __shared__ float4 smP[8][32];
    __shared__ float4 smQ[8][32];
    __shared__ int    scnt[256];
    const int tid  = threadIdx.x;
    const int d    = blockIdx.x >> 3;
    const int fs   = blockIdx.x & 7;
    const int w    = tid >> 5, lane = tid & 31;
    const int posIdx = fs * 32 + lane;
    const int oab  = d * FDIM + posIdx * 4;

    // Preload pure inputs BEFORE the grid-dep sync (overlap with stats tail).
    float4 gpre = make_float4(0.f, 0.f, 0.f, 0.f);
    float4 bpre = gpre;
    if (w == 0) {
        gpre = *(const float4*)(gamma + oab);
        bpre = *(const float4*)(beta + oab);
    }

    // Wait for stats' memory to be visible.
    cudaGridDependencySynchronize();
    // Let apply's grid launch now: it reads g_ydom (stats, complete) and x
    // (input) before ITS grid-dep sync, overlapping with this kernel.
    cudaTriggerProgrammaticLaunchCompletion();

    {
        int c = 0;
        for (int s = tid; s < nseg; s += 256) c += g_c[s * DDOM + d];
        scnt[tid] = c;
    }

    const float4* P4 = (const float4*)g_P;
    const float4* Q4 = (const float4*)g_Q;
    const size_t segstep = (size_t)DDOM * FV;
    const size_t ob = (size_t)d * FV + posIdx;

    float4 ap0 = make_float4(0.f, 0.f, 0.f, 0.f), ap1 = ap0, ap2 = ap0, ap3 = ap0;
    float4 aq0 = ap0, aq1 = ap0, aq2 = ap0, aq3 = ap0;
    int s = w;
    for (; s + 24 < nseg; s += 32) {
        const size_t o0 = ob + (size_t)s * segstep;
        const size_t o1 = o0 + 8 * segstep;
        const size_t o2 = o0 + 16 * segstep;
        const size_t o3 = o0 + 24 * segstep;
        float4 p0 = P4[o0], p1 = P4[o1], p2 = P4[o2], p3 = P4[o3];
        float4 q0 = Q4[o0], q1 = Q4[o1], q2 = Q4[o2], q3 = Q4[o3];
        FADD4(ap0, p0); FADD4(ap1, p1); FADD4(ap2, p2); FADD4(ap3, p3);
        FADD4(aq0, q0); FADD4(aq1, q1); FADD4(aq2, q2); FADD4(aq3, q3);
    }
    for (; s < nseg; s += 8) {
        const size_t o = ob + (size_t)s * segstep;
        float4 p = P4[o], q = Q4[o];
        FADD4(ap0, p); FADD4(aq0, q);
    }
    FADD4(ap0, ap1); FADD4(ap2, ap3); FADD4(ap0, ap2);
    FADD4(aq0, aq1); FADD4(aq2, aq3); FADD4(aq0, aq2);
    smP[w][lane] = ap0;
    smQ[w][lane] = aq0;
    __syncthreads();

    for (int off = 128; off > 0; off >>= 1) {
        if (tid < off) scnt[tid] += scnt[tid + off];
        __syncthreads();
    }
    const float c = (float)scnt[0];

    if (w == 0) {
        float4 s1 = smP[0][lane], s2 = smQ[0][lane];
#pragma unroll
        for (int ww = 1; ww < 8; ww++) {
            FADD4(s1, smP[ww][lane]);
            FADD4(s2, smQ[ww][lane]);
        }
        float4 A, Bv;
        if (c > 1.5f) {
            const float rc = 1.0f / c;
            float mx = s1.x * rc, my = s1.y * rc, mz = s1.z * rc, mw = s1.w * rc;
            float vx = fmaf(-mx, mx, s2.x * rc);
            float vy = fmaf(-my, my, s2.y * rc);
            float vz = fmaf(-mz, mz, s2.z * rc);
            float vw = fmaf(-mw, mw, s2.w * rc);
            A.x = gpre.x * rsqrtf(vx + EPSV);
            A.y = gpre.y * rsqrtf(vy + EPSV);
            A.z = gpre.z * rsqrtf(vz + EPSV);
            A.w = gpre.w * rsqrtf(vw + EPSV);
            Bv.x = fmaf(-mx, A.x, bpre.x);
            Bv.y = fmaf(-my, A.y, bpre.y);
            Bv.z = fmaf(-mz, A.z, bpre.z);
            Bv.w = fmaf(-mw, A.w, bpre.w);
        } else if (c > 0.5f) {   // single-sample domain: out = x
            A  = make_float4(1.f, 1.f, 1.f, 1.f);
            Bv = make_float4(0.f, 0.f, 0.f, 0.f);
        } else {                 // empty domain (unused)
            A  = make_float4(0.f, 0.f, 0.f, 0.f);
            Bv = make_float4(0.f, 0.f, 0.f, 0.f);
        }
        *(float4*)(g_A + oab) = A;
        *(float4*)(g_B + oab) = Bv;
    }
}

// ---- K3: out = A[d]*x + B[d]; x loads issued BEFORE grid-dep sync ----
__global__ __launch_bounds__(256)
void apply_k(const float4* __restrict__ x4, float4* __restrict__ o4, int n) {
    __shared__ int sd[RA];
    const int tid = threadIdx.x;
    const int r0  = blockIdx.x * RA;

    // g_ydom was written by stats, which completed before finalize's trigger
    // fired; this grid launches only after that trigger -> safe pre-sync.
    if (tid < RA) {
        const int r = r0 + tid;
        sd[tid] = (r < n) ? (int)g_ydom[r] : 0;
    }
    __syncthreads();

    const float4* A4 = (const float4*)g_A;
    const float4* B4 = (const float4*)g_B;

    if (r0 + RA <= n) {
        const float4* p = x4 + (size_t)r0 * FV + tid;
        float4 v[RA];
#pragma unroll
        for (int j = 0; j < RA; j++) v[j] = __ldcs(p + j * FV);   // input: pre-sync OK

        cudaGridDependencySynchronize();   // A/B ready after this

#pragma unroll
        for (int j = 0; j < RA; j++) {
            const int dd = sd[j];
            const float4 a = __ldg(A4 + dd * FV + tid);
            const float4 b = __ldg(B4 + dd * FV + tid);
            float4 w;
            w.x = fmaf(v[j].x, a.x, b.x);
            w.y = fmaf(v[j].y, a.y, b.y);
            w.z = fmaf(v[j].z, a.z, b.z);
            w.w = fmaf(v[j].w, a.w, b.w);
            __stcs(o4 + (size_t)(r0 + j) * FV + tid, w);
        }
    } else {
        cudaGridDependencySynchronize();
        for (int j = 0; j < RA; j++) {
            const int rr = r0 + j;
            if (rr >= n) break;
            const int dd = sd[j];
            float4 v = __ldcs(x4 + (size_t)rr * FV + tid);
            float4 a = __ldg(A4 + dd * FV + tid);
            float4 b = __ldg(B4 + dd * FV + tid);
            float4 w;
            w.x = fmaf(v.x, a.x, b.x); w.y = fmaf(v.y, a.y, b.y);
            w.z = fmaf(v.z, a.z, b.z); w.w = fmaf(v.w, a.w, b.w);
            __stcs(o4 + (size_t)rr * FV + tid, w);
        }
    }
}

extern "C" void kernel_launch(void* const* d_in, const int* in_sizes, int n_in,
                              void* d_out, int out_size) {
    const float* x     = (const float*)d_in[0];
    const int*   y     = (const int*)d_in[1];
    const float* gamma = (const float*)d_in[2];
    const float* beta  = (const float*)d_in[3];
    float* out = (float*)d_out;

    const int n   = in_sizes[1];
    const int rlo = n / NSEG;
    const int rem = n - rlo * NSEG;

    stats_k<<<NSEG, 256>>>((const float4*)x, y, n, rlo, rem);

    cudaLaunchAttribute attrs[1];
    attrs[0].id = cudaLaunchAttributeProgrammaticStreamSerialization;
    attrs[0].val.programmaticStreamSerializationAllowed = 1;

    {   // finalize: PDL secondary of stats
        cudaLaunchConfig_t cfg = {};
        cfg.gridDim  = dim3(DDOM * 8);
        cfg.blockDim = dim3(256);
        cfg.attrs = attrs;
        cfg.numAttrs = 1;
        cfg.stream = 0;
        cudaLaunchKernelEx(&cfg, finalize_k, gamma, beta, (int)NSEG);
    }
    {   // apply: PDL secondary of finalize
        cudaLaunchConfig_t cfg = {};
        cfg.gridDim  = dim3((n + RA - 1) / RA);
        cfg.blockDim = dim3(256);
        cfg.attrs = attrs;
        cfg.numAttrs = 1;
        cfg.stream = 0;
        cudaLaunchKernelEx(&cfg, apply_k, (const float4*)x, (float4*)out, n);
    }
}